// round 3
// baseline (speedup 1.0000x reference)
#include <cuda_runtime.h>
#include <cstdint>
#include <math.h>

#define NT      2048
#define DMODEL  2048
#define NHEAD   16
#define DHEAD   128
#define INNERD  2048
#define FFI     8192
#define VOCAB   32000
#define NLAYER  4
#define EPSF    1e-5f
#define MASKV   1e-10f

// ---------------- scratch (static device globals; no allocations) ----------------
__device__ float g_x [NT * DMODEL];   // residual stream
__device__ float g_h [NT * DMODEL];   // normed activations
__device__ float g_q [NT * INNERD];   // q projections
__device__ float g_k [NT * DHEAD];    // shared k head
__device__ float g_v [NT * DHEAD];    // shared v head
__device__ float g_ao[NT * INNERD];   // attention output (pre o-proj)
__device__ float g_f1[NT * FFI];      // ffn wi branch
__device__ float g_f2[NT * FFI];      // ffn wg branch

// ---------------- embedding lookup ----------------
__global__ void embed_kernel(const int* __restrict__ tok,
                             const float* __restrict__ emb,
                             float* __restrict__ x) {
    int n = blockIdx.x;
    int t = tok[n];
    const float* src = emb + (size_t)t * DMODEL;
    float* dst = x + (size_t)n * DMODEL;
    for (int d = threadIdx.x; d < DMODEL; d += blockDim.x)
        dst[d] = src[d];
}

// ---------------- RMSNorm (one block per row) ----------------
__global__ void __launch_bounds__(256) rmsnorm_kernel(const float* __restrict__ x,
                                                      const float* __restrict__ gamma,
                                                      float* __restrict__ o) {
    int n = blockIdx.x;
    const float* row = x + (size_t)n * DMODEL;
    float s = 0.f;
    for (int d = threadIdx.x; d < DMODEL; d += 256) {
        float v = row[d];
        s += v * v;
    }
    __shared__ float red[256];
    red[threadIdx.x] = s;
    __syncthreads();
    #pragma unroll
    for (int k = 128; k > 0; k >>= 1) {
        if (threadIdx.x < k) red[threadIdx.x] += red[threadIdx.x + k];
        __syncthreads();
    }
    float inv = rsqrtf(red[0] * (1.0f / DMODEL) + EPSF);
    float* dst = o + (size_t)n * DMODEL;
    for (int d = threadIdx.x; d < DMODEL; d += 256)
        dst[d] = row[d] * inv * gamma[d];
}

// ---------------- tiled SGEMM: C[M,N] = A[M,K] @ B  (+= if ACC) ----------------
// TRANSB==0: B is [K,N] row-major.  TRANSB==1: B is [N,K] row-major (C = A @ B^T).
// Requires M%128==0, N%128==0, K%16==0 (true for all shapes here).
template <int TRANSB, int ACC>
__global__ void __launch_bounds__(256) sgemm_kernel(const float* __restrict__ A,
                                                    const float* __restrict__ B,
                                                    float* __restrict__ C,
                                                    int M, int Nn, int K) {
    __shared__ float As[16][128];
    __shared__ float Bs[16][128];
    const int tid = threadIdx.x;
    const int rowBase = blockIdx.y * 128;
    const int colBase = blockIdx.x * 128;
    const int ty = tid >> 4;   // 0..15
    const int tx = tid & 15;   // 0..15

    float acc[8][8];
    #pragma unroll
    for (int m = 0; m < 8; ++m)
        #pragma unroll
        for (int n = 0; n < 8; ++n) acc[m][n] = 0.f;

    for (int kt = 0; kt < K; kt += 16) {
        #pragma unroll
        for (int r = 0; r < 2; ++r) {
            int idx = tid + r * 256;           // 0..511
            // ---- A tile: 128 rows x 16 k, loaded as float4 along k, stored transposed
            {
                int ar = idx >> 2;
                int ac = (idx & 3) * 4;
                float4 a = *(const float4*)(A + (size_t)(rowBase + ar) * K + kt + ac);
                As[ac + 0][ar] = a.x;
                As[ac + 1][ar] = a.y;
                As[ac + 2][ar] = a.z;
                As[ac + 3][ar] = a.w;
            }
            // ---- B tile
            if (TRANSB) {
                int bn = idx >> 2;
                int bk = (idx & 3) * 4;
                float4 b = *(const float4*)(B + (size_t)(colBase + bn) * K + kt + bk);
                Bs[bk + 0][bn] = b.x;
                Bs[bk + 1][bn] = b.y;
                Bs[bk + 2][bn] = b.z;
                Bs[bk + 3][bn] = b.w;
            } else {
                int bk = idx >> 5;
                int bn = (idx & 31) * 4;
                float4 b = *(const float4*)(B + (size_t)(kt + bk) * Nn + colBase + bn);
                *(float4*)&Bs[bk][bn] = b;
            }
        }
        __syncthreads();

        #pragma unroll
        for (int kk = 0; kk < 16; ++kk) {
            float ra[8], rb[8];
            *(float4*)&ra[0] = *(const float4*)&As[kk][ty * 8];
            *(float4*)&ra[4] = *(const float4*)&As[kk][ty * 8 + 4];
            *(float4*)&rb[0] = *(const float4*)&Bs[kk][tx * 8];
            *(float4*)&rb[4] = *(const float4*)&Bs[kk][tx * 8 + 4];
            #pragma unroll
            for (int m = 0; m < 8; ++m)
                #pragma unroll
                for (int n = 0; n < 8; ++n)
                    acc[m][n] += ra[m] * rb[n];
        }
        __syncthreads();
    }

    #pragma unroll
    for (int m = 0; m < 8; ++m) {
        float* crow = C + (size_t)(rowBase + ty * 8 + m) * Nn + colBase + tx * 8;
        #pragma unroll
        for (int n = 0; n < 8; ++n) {
            if (ACC) crow[n] += acc[m][n];
            else     crow[n]  = acc[m][n];
        }
    }
}

// ---------------- attention: one CTA per (query i, head h) ----------------
// Faithful semantics: sim = q.k*scale + slope*j for j<=i, else MASK_VALUE(=1e-10),
// then full softmax over ALL N columns (masked entries participate).
__global__ void __launch_bounds__(128) attn_kernel(const float* __restrict__ q,
                                                   const float* __restrict__ k,
                                                   const float* __restrict__ v,
                                                   float* __restrict__ o) {
    const int i   = blockIdx.x;
    const int h   = blockIdx.y;
    const int tid = threadIdx.x;

    __shared__ float qs[DHEAD];
    __shared__ float sc[NT];
    __shared__ float red[128];

    // q row for this head, scaled by DH^-0.5 = 1/sqrt(128)
    qs[tid] = q[(size_t)i * INNERD + h * DHEAD + tid] * 0.08838834764831845f;
    __syncthreads();

    const float slope = exp2f(-0.5f * (float)(h + 1));

    // scores
    for (int j = tid; j < NT; j += 128) {
        float val;
        if (j <= i) {
            const float4* kp = (const float4*)(k + (size_t)j * DHEAD);
            const float4* qp = (const float4*)qs;
            float dot = 0.f;
            #pragma unroll
            for (int d = 0; d < DHEAD / 4; ++d) {
                float4 kv = kp[d];
                float4 qv = qp[d];
                dot += qv.x * kv.x + qv.y * kv.y + qv.z * kv.z + qv.w * kv.w;
            }
            val = dot + slope * (float)j;
        } else {
            val = MASKV;
        }
        sc[j] = val;
    }
    __syncthreads();

    // row max
    float mx = -3.4e38f;
    for (int j = tid; j < NT; j += 128) mx = fmaxf(mx, sc[j]);
    red[tid] = mx;
    __syncthreads();
    #pragma unroll
    for (int s = 64; s > 0; s >>= 1) {
        if (tid < s) red[tid] = fmaxf(red[tid], red[tid + s]);
        __syncthreads();
    }
    mx = red[0];
    __syncthreads();

    // exp + sum
    float sum = 0.f;
    for (int j = tid; j < NT; j += 128) {
        float p = expf(sc[j] - mx);
        sc[j] = p;
        sum += p;
    }
    red[tid] = sum;
    __syncthreads();
    #pragma unroll
    for (int s = 64; s > 0; s >>= 1) {
        if (tid < s) red[tid] += red[tid + s];
        __syncthreads();
    }
    const float inv = 1.f / red[0];

    // out[i, h*DH + d] = sum_j p[j] * v[j, d] / Z   (thread = one d; coalesced v reads)
    float acc = 0.f;
    const int d = tid;
    #pragma unroll 4
    for (int j = 0; j < NT; ++j)
        acc += sc[j] * v[(size_t)j * DHEAD + d];
    o[(size_t)i * INNERD + h * DHEAD + d] = acc * inv;
}

// ---------------- SwiGLU gate: a = a * b * sigmoid(b) ----------------
__global__ void silu_mul_kernel(float* __restrict__ a, const float* __restrict__ b, int n) {
    int i = blockIdx.x * blockDim.x + threadIdx.x;
    if (i < n) {
        float bb = b[i];
        a[i] = a[i] * bb / (1.f + expf(-bb));
    }
}

// ---------------- host-side GEMM dispatch ----------------
static void gemm(const float* A, const float* B, float* C,
                 int M, int Nn, int K, bool transb, bool acc) {
    dim3 grid(Nn / 128, M / 128), block(256);
    if (transb) {
        if (acc) sgemm_kernel<1, 1><<<grid, block>>>(A, B, C, M, Nn, K);
        else     sgemm_kernel<1, 0><<<grid, block>>>(A, B, C, M, Nn, K);
    } else {
        if (acc) sgemm_kernel<0, 1><<<grid, block>>>(A, B, C, M, Nn, K);
        else     sgemm_kernel<0, 0><<<grid, block>>>(A, B, C, M, Nn, K);
    }
}

extern "C" void kernel_launch(void* const* d_in, const int* in_sizes, int n_in,
                              void* d_out, int out_size) {
    const int*   tokens      = (const int*)  d_in[0];
    const float* emb         = (const float*)d_in[1];
    const float* attn_gamma  = (const float*)d_in[2];
    const float* wq          = (const float*)d_in[3];
    const float* wk          = (const float*)d_in[4];
    const float* wv          = (const float*)d_in[5];
    const float* wo          = (const float*)d_in[6];
    const float* ff_gamma    = (const float*)d_in[7];
    const float* wi          = (const float*)d_in[8];
    const float* wg          = (const float*)d_in[9];
    const float* wfo         = (const float*)d_in[10];
    const float* final_gamma = (const float*)d_in[11];
    float* out = (float*)d_out;

    float *x, *h, *q, *k, *v, *ao, *f1, *f2;
    cudaGetSymbolAddress((void**)&x,  g_x);
    cudaGetSymbolAddress((void**)&h,  g_h);
    cudaGetSymbolAddress((void**)&q,  g_q);
    cudaGetSymbolAddress((void**)&k,  g_k);
    cudaGetSymbolAddress((void**)&v,  g_v);
    cudaGetSymbolAddress((void**)&ao, g_ao);
    cudaGetSymbolAddress((void**)&f1, g_f1);
    cudaGetSymbolAddress((void**)&f2, g_f2);

    embed_kernel<<<NT, 256>>>(tokens, emb, x);

    for (int l = 0; l < NLAYER; ++l) {
        // --- attention block ---
        rmsnorm_kernel<<<NT, 256>>>(x, attn_gamma + (size_t)l * DMODEL, h);
        gemm(h, wq + (size_t)l * DMODEL * INNERD, q, NT, INNERD, DMODEL, false, false);
        gemm(h, wk + (size_t)l * DMODEL * DHEAD,  k, NT, DHEAD,  DMODEL, false, false);
        gemm(h, wv + (size_t)l * DMODEL * DHEAD,  v, NT, DHEAD,  DMODEL, false, false);
        attn_kernel<<<dim3(NT, NHEAD), 128>>>(q, k, v, ao);
        gemm(ao, wo + (size_t)l * INNERD * DMODEL, x, NT, DMODEL, INNERD, false, true);  // x += ao@wo

        // --- SwiGLU FFN ---
        rmsnorm_kernel<<<NT, 256>>>(x, ff_gamma + (size_t)l * DMODEL, h);
        gemm(h, wi + (size_t)l * DMODEL * FFI, f1, NT, FFI, DMODEL, false, false);
        gemm(h, wg + (size_t)l * DMODEL * FFI, f2, NT, FFI, DMODEL, false, false);
        silu_mul_kernel<<<(NT * FFI) / 256, 256>>>(f1, f2, NT * FFI);
        gemm(f1, wfo + (size_t)l * FFI * DMODEL, x, NT, DMODEL, FFI, false, true);       // x += hidden@wfo
    }

    // --- final norm + logits ---
    rmsnorm_kernel<<<NT, 256>>>(x, final_gamma, h);
    gemm(h, emb, out, NT, VOCAB, DMODEL, true, false);   // out = h @ emb^T
}

// round 4
// speedup vs baseline: 1.4131x; 1.4131x over previous
#include <cuda_runtime.h>
#include <cuda_bf16.h>
#include <cstdint>
#include <math.h>

#define NT      2048
#define DMODEL  2048
#define NHEAD   16
#define DHEAD   128
#define INNERD  2048
#define FFI     8192
#define VOCAB   32000
#define NLAYER  4
#define EPSF    1e-5f
#define MASKV   1e-10f

// ---------------- scratch (static device globals; no allocations) ----------------
__device__ float g_x [NT * DMODEL];   // residual stream
__device__ float g_h [NT * DMODEL];   // normed activations
__device__ float g_q [NT * INNERD];   // q projections
__device__ float g_k [NT * DHEAD];    // shared k head
__device__ float g_v [NT * DHEAD];    // shared v head
__device__ float g_ao[NT * INNERD];   // attention output (pre o-proj)
__device__ float g_f1[NT * FFI];      // ffn wi branch
__device__ float g_f2[NT * FFI];      // ffn wg branch

// ---------------- embedding lookup ----------------
__global__ void embed_kernel(const int* __restrict__ tok,
                             const float* __restrict__ emb,
                             float* __restrict__ x) {
    int n = blockIdx.x;
    int t = tok[n];
    const float* src = emb + (size_t)t * DMODEL;
    float* dst = x + (size_t)n * DMODEL;
    for (int d = threadIdx.x; d < DMODEL; d += blockDim.x)
        dst[d] = src[d];
}

// ---------------- RMSNorm (one block per row) ----------------
__global__ void __launch_bounds__(256) rmsnorm_kernel(const float* __restrict__ x,
                                                      const float* __restrict__ gamma,
                                                      float* __restrict__ o) {
    int n = blockIdx.x;
    const float* row = x + (size_t)n * DMODEL;
    float s = 0.f;
    for (int d = threadIdx.x; d < DMODEL; d += 256) {
        float v = row[d];
        s += v * v;
    }
    __shared__ float red[256];
    red[threadIdx.x] = s;
    __syncthreads();
    #pragma unroll
    for (int k = 128; k > 0; k >>= 1) {
        if (threadIdx.x < k) red[threadIdx.x] += red[threadIdx.x + k];
        __syncthreads();
    }
    float inv = rsqrtf(red[0] * (1.0f / DMODEL) + EPSF);
    float* dst = o + (size_t)n * DMODEL;
    for (int d = threadIdx.x; d < DMODEL; d += 256)
        dst[d] = row[d] * inv * gamma[d];
}

// ================= bf16-split tensor-core GEMM =================
// C[M,N] = A[M,K] @ B (+= if ACC), fp32 in/out.
// Each fp32 is split x = hi + lo (both bf16); product uses 3 mmas:
//   hi*hi + hi*lo + lo*hi  (~2^-16 effective precision, fp32 accum).
// TRANSB==0: B is [K,N] row-major. TRANSB==1: B is [N,K] row-major (C=A@B^T).
// Requires M%128==0, N%128==0, K%32==0 (all shapes here qualify).

#define ASTR 40    // A smem row stride (elems) -> conflict-free ldmatrix
#define BSTR 136   // B smem row stride (elems) -> conflict-free ldmatrix

__device__ __forceinline__ uint32_t cvta_smem(const void* p) {
    return (uint32_t)__cvta_generic_to_shared(p);
}
__device__ __forceinline__ void ldsm4(uint32_t& r0, uint32_t& r1, uint32_t& r2, uint32_t& r3, uint32_t a) {
    asm volatile("ldmatrix.sync.aligned.m8n8.x4.shared.b16 {%0,%1,%2,%3},[%4];"
                 : "=r"(r0), "=r"(r1), "=r"(r2), "=r"(r3) : "r"(a));
}
__device__ __forceinline__ void ldsm4t(uint32_t& r0, uint32_t& r1, uint32_t& r2, uint32_t& r3, uint32_t a) {
    asm volatile("ldmatrix.sync.aligned.m8n8.x4.trans.shared.b16 {%0,%1,%2,%3},[%4];"
                 : "=r"(r0), "=r"(r1), "=r"(r2), "=r"(r3) : "r"(a));
}
__device__ __forceinline__ void mma16816(float* c, const uint32_t* a, const uint32_t* b) {
    asm volatile("mma.sync.aligned.m16n8k16.row.col.f32.bf16.bf16.f32 "
                 "{%0,%1,%2,%3},{%4,%5,%6,%7},{%8,%9},{%0,%1,%2,%3};"
                 : "+f"(c[0]), "+f"(c[1]), "+f"(c[2]), "+f"(c[3])
                 : "r"(a[0]), "r"(a[1]), "r"(a[2]), "r"(a[3]), "r"(b[0]), "r"(b[1]));
}
__device__ __forceinline__ void split_store2(uint16_t* hi, uint16_t* lo, float a, float b) {
    float ha = __bfloat162float(__float2bfloat16_rn(a));
    float hb = __bfloat162float(__float2bfloat16_rn(b));
    __nv_bfloat162 H = __floats2bfloat162_rn(a, b);
    __nv_bfloat162 L = __floats2bfloat162_rn(a - ha, b - hb);
    *(uint32_t*)hi = *(uint32_t*)&H;
    *(uint32_t*)lo = *(uint32_t*)&L;
}
__device__ __forceinline__ void split_store1(uint16_t* hi, uint16_t* lo, float a) {
    __nv_bfloat16 h = __float2bfloat16_rn(a);
    __nv_bfloat16 l = __float2bfloat16_rn(a - __bfloat162float(h));
    *hi = *(uint16_t*)&h;
    *lo = *(uint16_t*)&l;
}

template <int TRANSB, int ACC>
__global__ void __launch_bounds__(256, 2) gemm_tc_kernel(const float* __restrict__ A,
                                                         const float* __restrict__ B,
                                                         float* __restrict__ C,
                                                         int M, int N, int K) {
    __shared__ uint16_t sAh[128 * ASTR], sAl[128 * ASTR];
    __shared__ uint16_t sBh[32 * BSTR],  sBl[32 * BSTR];

    const int tid  = threadIdx.x;
    const int lane = tid & 31;
    const int warp = tid >> 5;
    const int wm = warp >> 2;   // 0..1  (64-row slab)
    const int wn = warp & 3;    // 0..3  (32-col slab)
    const int rowBase = blockIdx.y * 128;
    const int colBase = blockIdx.x * 128;

    float acc[4][4][4];
    #pragma unroll
    for (int i = 0; i < 4; ++i)
        #pragma unroll
        for (int j = 0; j < 4; ++j)
            #pragma unroll
            for (int v = 0; v < 4; ++v) acc[i][j][v] = 0.f;

    const int l15 = lane & 15;
    const int lhi = (lane >> 4) * 8;
    const uint32_t aBaseH = cvta_smem(sAh) + (((wm * 64 + l15) * ASTR + lhi) << 1);
    const uint32_t aBaseL = cvta_smem(sAl) + (((wm * 64 + l15) * ASTR + lhi) << 1);
    const uint32_t bBaseH = cvta_smem(sBh) + ((l15 * BSTR + wn * 32 + lhi) << 1);
    const uint32_t bBaseL = cvta_smem(sBl) + ((l15 * BSTR + wn * 32 + lhi) << 1);

    float4 pA[4], pB[4];
    // -------- prologue global load (kt = 0) --------
    #pragma unroll
    for (int r = 0; r < 4; ++r) {
        int idx = tid + r * 256;
        { int row = idx >> 3, kq = (idx & 7) * 4;
          pA[r] = *(const float4*)(A + (size_t)(rowBase + row) * K + kq); }
        if (!TRANSB) {
            int kr = idx >> 5, nq = (idx & 31) * 4;
            pB[r] = *(const float4*)(B + (size_t)kr * N + colBase + nq);
        } else {
            int nr = idx >> 3, kq = (idx & 7) * 4;
            pB[r] = *(const float4*)(B + (size_t)(colBase + nr) * K + kq);
        }
    }

    for (int kt = 0; kt < K; kt += 32) {
        // -------- store current tile (with bf16 split) --------
        #pragma unroll
        for (int r = 0; r < 4; ++r) {
            int idx = tid + r * 256;
            { int row = idx >> 3, kq = (idx & 7) * 4;
              float4 v = pA[r];
              split_store2(&sAh[row * ASTR + kq],     &sAl[row * ASTR + kq],     v.x, v.y);
              split_store2(&sAh[row * ASTR + kq + 2], &sAl[row * ASTR + kq + 2], v.z, v.w); }
            if (!TRANSB) {
                int kr = idx >> 5, nq = (idx & 31) * 4;
                float4 v = pB[r];
                split_store2(&sBh[kr * BSTR + nq],     &sBl[kr * BSTR + nq],     v.x, v.y);
                split_store2(&sBh[kr * BSTR + nq + 2], &sBl[kr * BSTR + nq + 2], v.z, v.w);
            } else {
                int nr = idx >> 3, kq = (idx & 7) * 4;
                float4 v = pB[r];
                split_store1(&sBh[(kq + 0) * BSTR + nr], &sBl[(kq + 0) * BSTR + nr], v.x);
                split_store1(&sBh[(kq + 1) * BSTR + nr], &sBl[(kq + 1) * BSTR + nr], v.y);
                split_store1(&sBh[(kq + 2) * BSTR + nr], &sBl[(kq + 2) * BSTR + nr], v.z);
                split_store1(&sBh[(kq + 3) * BSTR + nr], &sBl[(kq + 3) * BSTR + nr], v.w);
            }
        }
        __syncthreads();

        // -------- prefetch next tile into registers --------
        if (kt + 32 < K) {
            #pragma unroll
            for (int r = 0; r < 4; ++r) {
                int idx = tid + r * 256;
                { int row = idx >> 3, kq = (idx & 7) * 4;
                  pA[r] = *(const float4*)(A + (size_t)(rowBase + row) * K + kt + 32 + kq); }
                if (!TRANSB) {
                    int kr = idx >> 5, nq = (idx & 31) * 4;
                    pB[r] = *(const float4*)(B + (size_t)(kt + 32 + kr) * N + colBase + nq);
                } else {
                    int nr = idx >> 3, kq = (idx & 7) * 4;
                    pB[r] = *(const float4*)(B + (size_t)(colBase + nr) * K + kt + 32 + kq);
                }
            }
        }

        // -------- compute: 2 k-steps of 16, 3 mma passes each --------
        #pragma unroll
        for (int ks = 0; ks < 32; ks += 16) {
            uint32_t aH[4][4], aL[4][4], bH[2][4], bL[2][4];
            #pragma unroll
            for (int mt = 0; mt < 4; ++mt)
                ldsm4(aH[mt][0], aH[mt][1], aH[mt][2], aH[mt][3],
                      aBaseH + mt * (16 * ASTR * 2) + ks * 2);
            #pragma unroll
            for (int p = 0; p < 2; ++p)
                ldsm4t(bH[p][0], bH[p][1], bH[p][2], bH[p][3],
                       bBaseH + ks * (BSTR * 2) + p * 32);
            #pragma unroll
            for (int mt = 0; mt < 4; ++mt)
                #pragma unroll
                for (int nt = 0; nt < 4; ++nt)
                    mma16816(acc[mt][nt], aH[mt], &bH[nt >> 1][(nt & 1) * 2]);

            #pragma unroll
            for (int p = 0; p < 2; ++p)
                ldsm4t(bL[p][0], bL[p][1], bL[p][2], bL[p][3],
                       bBaseL + ks * (BSTR * 2) + p * 32);
            #pragma unroll
            for (int mt = 0; mt < 4; ++mt)
                #pragma unroll
                for (int nt = 0; nt < 4; ++nt)
                    mma16816(acc[mt][nt], aH[mt], &bL[nt >> 1][(nt & 1) * 2]);

            #pragma unroll
            for (int mt = 0; mt < 4; ++mt)
                ldsm4(aL[mt][0], aL[mt][1], aL[mt][2], aL[mt][3],
                      aBaseL + mt * (16 * ASTR * 2) + ks * 2);
            #pragma unroll
            for (int mt = 0; mt < 4; ++mt)
                #pragma unroll
                for (int nt = 0; nt < 4; ++nt)
                    mma16816(acc[mt][nt], aL[mt], &bH[nt >> 1][(nt & 1) * 2]);
        }
        __syncthreads();
    }

    // -------- epilogue --------
    const int r0 = rowBase + wm * 64 + (lane >> 2);
    const int c0 = colBase + wn * 32 + (lane & 3) * 2;
    #pragma unroll
    for (int mt = 0; mt < 4; ++mt) {
        #pragma unroll
        for (int nt = 0; nt < 4; ++nt) {
            int r = r0 + mt * 16, c = c0 + nt * 8;
            float2* p0 = (float2*)(C + (size_t)r * N + c);
            float2* p1 = (float2*)(C + (size_t)(r + 8) * N + c);
            if (ACC) {
                float2 t0 = *p0, t1 = *p1;
                t0.x += acc[mt][nt][0]; t0.y += acc[mt][nt][1];
                t1.x += acc[mt][nt][2]; t1.y += acc[mt][nt][3];
                *p0 = t0; *p1 = t1;
            } else {
                float2 t0 = {acc[mt][nt][0], acc[mt][nt][1]};
                float2 t1 = {acc[mt][nt][2], acc[mt][nt][3]};
                *p0 = t0; *p1 = t1;
            }
        }
    }
}

// ---------------- attention: one CTA per (query i, head h) ----------------
__global__ void __launch_bounds__(128) attn_kernel(const float* __restrict__ q,
                                                   const float* __restrict__ k,
                                                   const float* __restrict__ v,
                                                   float* __restrict__ o) {
    const int i   = blockIdx.x;
    const int h   = blockIdx.y;
    const int tid = threadIdx.x;

    __shared__ float qs[DHEAD];
    __shared__ float sc[NT];
    __shared__ float red[128];

    qs[tid] = q[(size_t)i * INNERD + h * DHEAD + tid] * 0.08838834764831845f;
    __syncthreads();

    const float slope = exp2f(-0.5f * (float)(h + 1));

    for (int j = tid; j < NT; j += 128) {
        float val;
        if (j <= i) {
            const float4* kp = (const float4*)(k + (size_t)j * DHEAD);
            const float4* qp = (const float4*)qs;
            float dot = 0.f;
            #pragma unroll
            for (int d = 0; d < DHEAD / 4; ++d) {
                float4 kv = kp[d];
                float4 qv = qp[d];
                dot += qv.x * kv.x + qv.y * kv.y + qv.z * kv.z + qv.w * kv.w;
            }
            val = dot + slope * (float)j;
        } else {
            val = MASKV;
        }
        sc[j] = val;
    }
    __syncthreads();

    float mx = -3.4e38f;
    for (int j = tid; j < NT; j += 128) mx = fmaxf(mx, sc[j]);
    red[tid] = mx;
    __syncthreads();
    #pragma unroll
    for (int s = 64; s > 0; s >>= 1) {
        if (tid < s) red[tid] = fmaxf(red[tid], red[tid + s]);
        __syncthreads();
    }
    mx = red[0];
    __syncthreads();

    float sum = 0.f;
    for (int j = tid; j < NT; j += 128) {
        float p = expf(sc[j] - mx);
        sc[j] = p;
        sum += p;
    }
    red[tid] = sum;
    __syncthreads();
    #pragma unroll
    for (int s = 64; s > 0; s >>= 1) {
        if (tid < s) red[tid] += red[tid + s];
        __syncthreads();
    }
    const float inv = 1.f / red[0];

    float acc = 0.f;
    const int d = tid;
    #pragma unroll 4
    for (int j = 0; j < NT; ++j)
        acc += sc[j] * v[(size_t)j * DHEAD + d];
    o[(size_t)i * INNERD + h * DHEAD + d] = acc * inv;
}

// ---------------- SwiGLU gate: a = a * b * sigmoid(b) ----------------
__global__ void silu_mul_kernel(float* __restrict__ a, const float* __restrict__ b, int n) {
    int i = blockIdx.x * blockDim.x + threadIdx.x;
    if (i < n) {
        float bb = b[i];
        a[i] = a[i] * bb / (1.f + expf(-bb));
    }
}

// ---------------- host-side GEMM dispatch ----------------
static void gemm(const float* A, const float* B, float* C,
                 int M, int Nn, int K, bool transb, bool acc) {
    dim3 grid(Nn / 128, M / 128), block(256);
    if (transb) {
        if (acc) gemm_tc_kernel<1, 1><<<grid, block>>>(A, B, C, M, Nn, K);
        else     gemm_tc_kernel<1, 0><<<grid, block>>>(A, B, C, M, Nn, K);
    } else {
        if (acc) gemm_tc_kernel<0, 1><<<grid, block>>>(A, B, C, M, Nn, K);
        else     gemm_tc_kernel<0, 0><<<grid, block>>>(A, B, C, M, Nn, K);
    }
}

extern "C" void kernel_launch(void* const* d_in, const int* in_sizes, int n_in,
                              void* d_out, int out_size) {
    const int*   tokens      = (const int*)  d_in[0];
    const float* emb         = (const float*)d_in[1];
    const float* attn_gamma  = (const float*)d_in[2];
    const float* wq          = (const float*)d_in[3];
    const float* wk          = (const float*)d_in[4];
    const float* wv          = (const float*)d_in[5];
    const float* wo          = (const float*)d_in[6];
    const float* ff_gamma    = (const float*)d_in[7];
    const float* wi          = (const float*)d_in[8];
    const float* wg          = (const float*)d_in[9];
    const float* wfo         = (const float*)d_in[10];
    const float* final_gamma = (const float*)d_in[11];
    float* out = (float*)d_out;

    float *x, *h, *q, *k, *v, *ao, *f1, *f2;
    cudaGetSymbolAddress((void**)&x,  g_x);
    cudaGetSymbolAddress((void**)&h,  g_h);
    cudaGetSymbolAddress((void**)&q,  g_q);
    cudaGetSymbolAddress((void**)&k,  g_k);
    cudaGetSymbolAddress((void**)&v,  g_v);
    cudaGetSymbolAddress((void**)&ao, g_ao);
    cudaGetSymbolAddress((void**)&f1, g_f1);
    cudaGetSymbolAddress((void**)&f2, g_f2);

    embed_kernel<<<NT, 256>>>(tokens, emb, x);

    for (int l = 0; l < NLAYER; ++l) {
        // --- attention block ---
        rmsnorm_kernel<<<NT, 256>>>(x, attn_gamma + (size_t)l * DMODEL, h);
        gemm(h, wq + (size_t)l * DMODEL * INNERD, q, NT, INNERD, DMODEL, false, false);
        gemm(h, wk + (size_t)l * DMODEL * DHEAD,  k, NT, DHEAD,  DMODEL, false, false);
        gemm(h, wv + (size_t)l * DMODEL * DHEAD,  v, NT, DHEAD,  DMODEL, false, false);
        attn_kernel<<<dim3(NT, NHEAD), 128>>>(q, k, v, ao);
        gemm(ao, wo + (size_t)l * INNERD * DMODEL, x, NT, DMODEL, INNERD, false, true);  // x += ao@wo

        // --- SwiGLU FFN ---
        rmsnorm_kernel<<<NT, 256>>>(x, ff_gamma + (size_t)l * DMODEL, h);
        gemm(h, wi + (size_t)l * DMODEL * FFI, f1, NT, FFI, DMODEL, false, false);
        gemm(h, wg + (size_t)l * DMODEL * FFI, f2, NT, FFI, DMODEL, false, false);
        silu_mul_kernel<<<(NT * FFI) / 256, 256>>>(f1, f2, NT * FFI);
        gemm(f1, wfo + (size_t)l * FFI * DMODEL, x, NT, DMODEL, FFI, false, true);       // x += hidden@wfo
    }

    // --- final norm + logits ---
    rmsnorm_kernel<<<NT, 256>>>(x, final_gamma, h);
    gemm(h, emb, out, NT, VOCAB, DMODEL, true, false);   // out = h @ emb^T
}

// round 5
// speedup vs baseline: 4.6052x; 3.2589x over previous
#include <cuda_runtime.h>
#include <cuda_bf16.h>
#include <cstdint>
#include <math.h>

#define NT      2048
#define DMODEL  2048
#define NHEAD   16
#define DHEAD   128
#define INNERD  2048
#define FFI     8192
#define VOCAB   32000
#define NLAYER  4
#define EPSF    1e-5f
#define MASKV   1e-10f
#define KT      32
#define ASTR    40     // [row][k] smem stride (elems) for A and trans-B tiles
#define BSTRN   136    // [k][n] smem stride (elems) for NN B tiles

typedef __nv_bfloat16 bf16;

// ---------------- scratch (static device globals; no allocations) ----------------
__device__ float g_x [NT * DMODEL];
__device__ bf16  g_hh[NT * DMODEL], g_hl[NT * DMODEL];
__device__ bf16  g_qh[NT * INNERD], g_ql[NT * INNERD];
__device__ float g_k [NT * DHEAD],  g_v [NT * DHEAD];
__device__ bf16  g_kh[NT * DHEAD],  g_kl[NT * DHEAD];
__device__ bf16  g_vh[NT * DHEAD],  g_vl[NT * DHEAD];
__device__ float g_S [(size_t)NHEAD * NT * NT];
__device__ bf16  g_Ph[(size_t)NHEAD * NT * NT], g_Pl[(size_t)NHEAD * NT * NT];
__device__ bf16  g_aoh[NT * INNERD], g_aol[NT * INNERD];
__device__ float g_f1[NT * FFI], g_f2[NT * FFI];
__device__ bf16  g_f1h[NT * FFI], g_f1l[NT * FFI];
// pre-split weights
__device__ bf16 w_qh [NLAYER * DMODEL * INNERD], w_ql [NLAYER * DMODEL * INNERD];
__device__ bf16 w_kh [NLAYER * DMODEL * DHEAD],  w_kl [NLAYER * DMODEL * DHEAD];
__device__ bf16 w_vh [NLAYER * DMODEL * DHEAD],  w_vl [NLAYER * DMODEL * DHEAD];
__device__ bf16 w_oh [NLAYER * INNERD * DMODEL], w_ol [NLAYER * INNERD * DMODEL];
__device__ bf16 w_ih [(size_t)NLAYER * DMODEL * FFI], w_il [(size_t)NLAYER * DMODEL * FFI];
__device__ bf16 w_gh [(size_t)NLAYER * DMODEL * FFI], w_gl [(size_t)NLAYER * DMODEL * FFI];
__device__ bf16 w_foh[(size_t)NLAYER * FFI * DMODEL], w_fol[(size_t)NLAYER * FFI * DMODEL];
__device__ bf16 w_eh [(size_t)VOCAB * DMODEL], w_el [(size_t)VOCAB * DMODEL];

// ---------------- small helpers ----------------
__device__ __forceinline__ void cpa16(uint32_t dst, const void* src) {
    asm volatile("cp.async.cg.shared.global [%0],[%1],16;" :: "r"(dst), "l"(src));
}
__device__ __forceinline__ void ldsm4(uint32_t* r, uint32_t a) {
    asm volatile("ldmatrix.sync.aligned.m8n8.x4.shared.b16 {%0,%1,%2,%3},[%4];"
                 : "=r"(r[0]), "=r"(r[1]), "=r"(r[2]), "=r"(r[3]) : "r"(a));
}
__device__ __forceinline__ void ldsm4t(uint32_t* r, uint32_t a) {
    asm volatile("ldmatrix.sync.aligned.m8n8.x4.trans.shared.b16 {%0,%1,%2,%3},[%4];"
                 : "=r"(r[0]), "=r"(r[1]), "=r"(r[2]), "=r"(r[3]) : "r"(a));
}
__device__ __forceinline__ void mma16816(float* c, const uint32_t* a, uint32_t b0, uint32_t b1) {
    asm volatile("mma.sync.aligned.m16n8k16.row.col.f32.bf16.bf16.f32 "
                 "{%0,%1,%2,%3},{%4,%5,%6,%7},{%8,%9},{%0,%1,%2,%3};"
                 : "+f"(c[0]), "+f"(c[1]), "+f"(c[2]), "+f"(c[3])
                 : "r"(a[0]), "r"(a[1]), "r"(a[2]), "r"(a[3]), "r"(b0), "r"(b1));
}
__device__ __forceinline__ void split1(float a, bf16& h, bf16& l) {
    h = __float2bfloat16_rn(a);
    l = __float2bfloat16_rn(a - __bfloat162float(h));
}
__device__ __forceinline__ void split2_store(bf16* hp, bf16* lp, float a, float b) {
    float ha = __bfloat162float(__float2bfloat16_rn(a));
    float hb = __bfloat162float(__float2bfloat16_rn(b));
    __nv_bfloat162 H = __floats2bfloat162_rn(a, b);
    __nv_bfloat162 L = __floats2bfloat162_rn(a - ha, b - hb);
    *(uint32_t*)hp = *(uint32_t*)&H;
    *(uint32_t*)lp = *(uint32_t*)&L;
}

// ---------------- fp32 -> bf16 hi/lo pair conversion (grid covers n/4) ----------------
__global__ void __launch_bounds__(256) cvt_pair_kernel(const float* __restrict__ in,
                                                       bf16* __restrict__ ho,
                                                       bf16* __restrict__ lo) {
    size_t i = (size_t)blockIdx.x * 256 + threadIdx.x;
    float4 v = ((const float4*)in)[i];
    bf16 h0, l0, h1, l1, h2, l2, h3, l3;
    split1(v.x, h0, l0); split1(v.y, h1, l1);
    split1(v.z, h2, l2); split1(v.w, h3, l3);
    __nv_bfloat162 ha = {h0, h1}, hb = {h2, h3}, la = {l0, l1}, lb = {l2, l3};
    uint2 H = {*(uint32_t*)&ha, *(uint32_t*)&hb};
    uint2 L = {*(uint32_t*)&la, *(uint32_t*)&lb};
    ((uint2*)ho)[i] = H;
    ((uint2*)lo)[i] = L;
}

// ---------------- embedding ----------------
__global__ void embed_kernel(const int* __restrict__ tok, const float* __restrict__ emb,
                             float* __restrict__ x) {
    int n = blockIdx.x;
    const float* src = emb + (size_t)tok[n] * DMODEL;
    float* dst = x + (size_t)n * DMODEL;
    for (int d = threadIdx.x; d < DMODEL; d += blockDim.x) dst[d] = src[d];
}

// ---------------- RMSNorm -> bf16 pair ----------------
__global__ void __launch_bounds__(256) rmsnorm_pair_kernel(const float* __restrict__ x,
                                                           const float* __restrict__ gamma,
                                                           bf16* __restrict__ oh,
                                                           bf16* __restrict__ ol) {
    int n = blockIdx.x;
    const float* row = x + (size_t)n * DMODEL;
    float s = 0.f;
    for (int d = threadIdx.x; d < DMODEL; d += 256) { float v = row[d]; s += v * v; }
    __shared__ float red[256];
    red[threadIdx.x] = s;
    __syncthreads();
    #pragma unroll
    for (int k = 128; k > 0; k >>= 1) {
        if (threadIdx.x < k) red[threadIdx.x] += red[threadIdx.x + k];
        __syncthreads();
    }
    float inv = rsqrtf(red[0] * (1.0f / DMODEL) + EPSF);
    for (int d = threadIdx.x; d < DMODEL; d += 256) {
        float v = row[d] * inv * gamma[d];
        bf16 h, l; split1(v, h, l);
        oh[(size_t)n * DMODEL + d] = h;
        ol[(size_t)n * DMODEL + d] = l;
    }
}

// ---------------- SwiGLU -> bf16 pair ----------------
__global__ void __launch_bounds__(256) silu_pair_kernel(const float* __restrict__ a,
                                                        const float* __restrict__ b,
                                                        bf16* __restrict__ oh,
                                                        bf16* __restrict__ ol) {
    size_t i = (size_t)blockIdx.x * 256 + threadIdx.x;
    float bb = b[i];
    float v = a[i] * bb / (1.f + __expf(-bb));
    bf16 h, l; split1(v, h, l);
    oh[i] = h; ol[i] = l;
}

// ---------------- ALiBi + causal mask + softmax -> bf16 pair P ----------------
__global__ void __launch_bounds__(256) softmax_kernel(const float* __restrict__ S,
                                                      bf16* __restrict__ Ph,
                                                      bf16* __restrict__ Pl) {
    const int i = blockIdx.x, h = blockIdx.y, tid = threadIdx.x;
    const float* row = S + ((size_t)h * NT + i) * NT;
    __shared__ float sc[NT];
    __shared__ float red[256];
    const float slope = exp2f(-0.5f * (float)(h + 1));
    const float scale = 0.08838834764831845f;   // 128^-0.5

    float mx = -3.4e38f;
    for (int j = tid; j < NT; j += 256) {
        float v = (j <= i) ? row[j] * scale + slope * (float)j : MASKV;
        sc[j] = v;
        mx = fmaxf(mx, v);
    }
    red[tid] = mx; __syncthreads();
    #pragma unroll
    for (int s = 128; s > 0; s >>= 1) {
        if (tid < s) red[tid] = fmaxf(red[tid], red[tid + s]);
        __syncthreads();
    }
    mx = red[0]; __syncthreads();

    float sum = 0.f;
    for (int j = tid; j < NT; j += 256) {
        float p = exp2f((sc[j] - mx) * 1.4426950408889634f);
        sc[j] = p;
        sum += p;
    }
    red[tid] = sum; __syncthreads();
    #pragma unroll
    for (int s = 128; s > 0; s >>= 1) {
        if (tid < s) red[tid] += red[tid + s];
        __syncthreads();
    }
    const float inv = 1.f / red[0];

    bf16* ph = Ph + ((size_t)h * NT + i) * NT;
    bf16* pl = Pl + ((size_t)h * NT + i) * NT;
    for (int j = tid; j < NT; j += 256) {
        bf16 hh, ll; split1(sc[j] * inv, hh, ll);
        ph[j] = hh; pl[j] = ll;
    }
}

// ================= pipelined bf16-split tensor-core GEMM =================
// C = A@B (NN) or A@B^T (TRANSB), inputs pre-split bf16 pairs, fp32 accum.
// EPI: 0 = store fp32, 1 = fp32 +=, 2 = fp32 atomicAdd (split-K), 3 = store bf16 pair.
// blockIdx.z: k-chunk if kSplit>1, else batch index with aZ/bZ/cZ element strides.
template <int TRANSB, int EPI>
__global__ void __launch_bounds__(256, 2)
gemm_bf3(const bf16* __restrict__ Ah, const bf16* __restrict__ Al,
         const bf16* __restrict__ Bh, const bf16* __restrict__ Bl,
         float* __restrict__ C, bf16* __restrict__ Ch, bf16* __restrict__ Cl,
         int M, int N, int K, int lda, int ldb, int ldc,
         int kSplit, size_t aZ, size_t bZ, size_t cZ) {
    extern __shared__ __align__(16) char smem[];
    const int tid = threadIdx.x, lane = tid & 31, warp = tid >> 5;
    const int wm = warp >> 2, wn = warp & 3;
    const int rowBase = blockIdx.y * 128, colBase = blockIdx.x * 128;
    const int z = blockIdx.z;
    int kStart = 0, kEnd = K;
    if (kSplit > 1) {
        int kl = K / kSplit; kStart = z * kl; kEnd = kStart + kl;
    } else {
        Ah += z * aZ; Al += z * aZ; Bh += z * bZ; Bl += z * bZ;
        if (EPI == 3) { Ch += z * cZ; Cl += z * cZ; } else { C += z * cZ; }
    }
    const int nk = (kEnd - kStart) / KT;
    const uint32_t sb = (uint32_t)__cvta_generic_to_shared(smem);
    const int BUFB = TRANSB ? 10240 : 8704;   // bytes per B half-buffer

    auto load_stage = [&](int s, int kt) {
        uint32_t aOff = sb + s * 20480;
        uint32_t bOff = sb + 40960 + s * 2 * BUFB;
        #pragma unroll
        for (int r = 0; r < 2; ++r) {
            int idx = tid + r * 256;
            int row = idx >> 2, kc = (idx & 3) * 8;
            uint32_t d = aOff + (row * ASTR + kc) * 2;
            const size_t ga = (size_t)(rowBase + row) * lda + kt + kc;
            cpa16(d,         Ah + ga);
            cpa16(d + 10240, Al + ga);
            if (!TRANSB) {
                int kr = idx >> 4, nc = (idx & 15) * 8;
                uint32_t db = bOff + (kr * BSTRN + nc) * 2;
                const size_t gb = (size_t)(kt + kr) * ldb + colBase + nc;
                cpa16(db,        Bh + gb);
                cpa16(db + BUFB, Bl + gb);
            } else {
                int nr = idx >> 2, kc2 = (idx & 3) * 8;
                uint32_t db = bOff + (nr * ASTR + kc2) * 2;
                const size_t gb = (size_t)(colBase + nr) * ldb + kt + kc2;
                cpa16(db,        Bh + gb);
                cpa16(db + BUFB, Bl + gb);
            }
        }
        asm volatile("cp.async.commit_group;");
    };

    float acc[4][4][4];
    #pragma unroll
    for (int i = 0; i < 4; ++i)
        #pragma unroll
        for (int j = 0; j < 4; ++j)
            #pragma unroll
            for (int v = 0; v < 4; ++v) acc[i][j][v] = 0.f;

    const int l15 = lane & 15, lhi = (lane >> 4) * 8;

    load_stage(0, kStart);

    for (int it = 0; it < nk; ++it) {
        const int s = it & 1;
        if (it + 1 < nk) {
            load_stage((it + 1) & 1, kStart + (it + 1) * KT);
            asm volatile("cp.async.wait_group 1;");
        } else {
            asm volatile("cp.async.wait_group 0;");
        }
        __syncthreads();

        const uint32_t aBase = sb + s * 20480 + ((wm * 64 + l15) * ASTR + lhi) * 2;
        const uint32_t bOff  = sb + 40960 + s * 2 * BUFB;

        #pragma unroll
        for (int ks = 0; ks < KT; ks += 16) {
            uint32_t aH[4][4], aL[4][4], bH[2][4], bL[2][4];
            #pragma unroll
            for (int mt = 0; mt < 4; ++mt)
                ldsm4(aH[mt], aBase + ks * 2 + mt * (16 * ASTR * 2));
            if (!TRANSB) {
                uint32_t bBase = bOff + ((l15 + ks) * BSTRN + wn * 32 + lhi) * 2;
                #pragma unroll
                for (int p = 0; p < 2; ++p) ldsm4t(bH[p], bBase + p * 32);
            } else {
                #pragma unroll
                for (int p = 0; p < 2; ++p)
                    ldsm4(bH[p], bOff + ((wn * 32 + p * 16 + l15) * ASTR + ks + lhi) * 2);
            }
            #pragma unroll
            for (int mt = 0; mt < 4; ++mt)
                #pragma unroll
                for (int nt = 0; nt < 4; ++nt) {
                    int p = nt >> 1, su = nt & 1;
                    uint32_t b0 = TRANSB ? bH[p][su]     : bH[p][2 * su];
                    uint32_t b1 = TRANSB ? bH[p][su + 2] : bH[p][2 * su + 1];
                    mma16816(acc[mt][nt], aH[mt], b0, b1);
                }
            // lo-B pass
            if (!TRANSB) {
                uint32_t bBase = bOff + BUFB + ((l15 + ks) * BSTRN + wn * 32 + lhi) * 2;
                #pragma unroll
                for (int p = 0; p < 2; ++p) ldsm4t(bL[p], bBase + p * 32);
            } else {
                #pragma unroll
                for (int p = 0; p < 2; ++p)
                    ldsm4(bL[p], bOff + BUFB + ((wn * 32 + p * 16 + l15) * ASTR + ks + lhi) * 2);
            }
            #pragma unroll
            for (int mt = 0; mt < 4; ++mt)
                #pragma unroll
                for (int nt = 0; nt < 4; ++nt) {
                    int p = nt >> 1, su = nt & 1;
                    uint32_t b0 = TRANSB ? bL[p][su]     : bL[p][2 * su];
                    uint32_t b1 = TRANSB ? bL[p][su + 2] : bL[p][2 * su + 1];
                    mma16816(acc[mt][nt], aH[mt], b0, b1);
                }
            // lo-A pass
            #pragma unroll
            for (int mt = 0; mt < 4; ++mt)
                ldsm4(aL[mt], aBase + 10240 + ks * 2 + mt * (16 * ASTR * 2));
            #pragma unroll
            for (int mt = 0; mt < 4; ++mt)
                #pragma unroll
                for (int nt = 0; nt < 4; ++nt) {
                    int p = nt >> 1, su = nt & 1;
                    uint32_t b0 = TRANSB ? bH[p][su]     : bH[p][2 * su];
                    uint32_t b1 = TRANSB ? bH[p][su + 2] : bH[p][2 * su + 1];
                    mma16816(acc[mt][nt], aL[mt], b0, b1);
                }
        }
        __syncthreads();
    }

    // ---------- epilogue ----------
    const int r0 = rowBase + wm * 64 + (lane >> 2);
    const int c0 = colBase + wn * 32 + (lane & 3) * 2;
    #pragma unroll
    for (int mt = 0; mt < 4; ++mt) {
        #pragma unroll
        for (int nt = 0; nt < 4; ++nt) {
            int r = r0 + mt * 16, c = c0 + nt * 8;
            if (EPI == 3) {
                split2_store(Ch + (size_t)r * ldc + c,       Cl + (size_t)r * ldc + c,
                             acc[mt][nt][0], acc[mt][nt][1]);
                split2_store(Ch + (size_t)(r + 8) * ldc + c, Cl + (size_t)(r + 8) * ldc + c,
                             acc[mt][nt][2], acc[mt][nt][3]);
            } else if (EPI == 2) {
                atomicAdd(C + (size_t)r * ldc + c,           acc[mt][nt][0]);
                atomicAdd(C + (size_t)r * ldc + c + 1,       acc[mt][nt][1]);
                atomicAdd(C + (size_t)(r + 8) * ldc + c,     acc[mt][nt][2]);
                atomicAdd(C + (size_t)(r + 8) * ldc + c + 1, acc[mt][nt][3]);
            } else {
                float2* p0 = (float2*)(C + (size_t)r * ldc + c);
                float2* p1 = (float2*)(C + (size_t)(r + 8) * ldc + c);
                if (EPI == 1) {
                    float2 t0 = *p0, t1 = *p1;
                    t0.x += acc[mt][nt][0]; t0.y += acc[mt][nt][1];
                    t1.x += acc[mt][nt][2]; t1.y += acc[mt][nt][3];
                    *p0 = t0; *p1 = t1;
                } else {
                    *p0 = make_float2(acc[mt][nt][0], acc[mt][nt][1]);
                    *p1 = make_float2(acc[mt][nt][2], acc[mt][nt][3]);
                }
            }
        }
    }
}

// ---------------- host-side dispatch ----------------
template <int TRANSB, int EPI>
static void launch_gemm(const bf16* Ah, const bf16* Al, const bf16* Bh, const bf16* Bl,
                        float* C, bf16* Ch, bf16* Cl,
                        int M, int N, int K, int lda, int ldb, int ldc,
                        int Z, int kSplit, size_t aZ, size_t bZ, size_t cZ) {
    const int smem = 40960 + 4 * (TRANSB ? 10240 : 8704);
    cudaFuncSetAttribute(gemm_bf3<TRANSB, EPI>, cudaFuncAttributeMaxDynamicSharedMemorySize, smem);
    dim3 grid(N / 128, M / 128, Z);
    gemm_bf3<TRANSB, EPI><<<grid, 256, smem>>>(Ah, Al, Bh, Bl, C, Ch, Cl,
                                               M, N, K, lda, ldb, ldc, kSplit, aZ, bZ, cZ);
}

extern "C" void kernel_launch(void* const* d_in, const int* in_sizes, int n_in,
                              void* d_out, int out_size) {
    const int*   tokens      = (const int*)  d_in[0];
    const float* emb         = (const float*)d_in[1];
    const float* attn_gamma  = (const float*)d_in[2];
    const float* wq          = (const float*)d_in[3];
    const float* wk          = (const float*)d_in[4];
    const float* wv          = (const float*)d_in[5];
    const float* wo          = (const float*)d_in[6];
    const float* ff_gamma    = (const float*)d_in[7];
    const float* wi          = (const float*)d_in[8];
    const float* wg          = (const float*)d_in[9];
    const float* wfo         = (const float*)d_in[10];
    const float* final_gamma = (const float*)d_in[11];
    float* out = (float*)d_out;

    float *x, *k, *v, *S, *f1, *f2;
    bf16 *hh, *hl, *qh, *ql, *kh, *kl, *vh, *vl, *Ph, *Pl, *aoh, *aol, *f1h, *f1l;
    bf16 *Wqh, *Wql, *Wkh, *Wkl, *Wvh, *Wvl, *Woh, *Wol, *Wih, *Wil, *Wgh, *Wgl, *Wfoh, *Wfol, *Weh, *Wel;
    cudaGetSymbolAddress((void**)&x,   g_x);
    cudaGetSymbolAddress((void**)&hh,  g_hh);  cudaGetSymbolAddress((void**)&hl,  g_hl);
    cudaGetSymbolAddress((void**)&qh,  g_qh);  cudaGetSymbolAddress((void**)&ql,  g_ql);
    cudaGetSymbolAddress((void**)&k,   g_k);   cudaGetSymbolAddress((void**)&v,   g_v);
    cudaGetSymbolAddress((void**)&kh,  g_kh);  cudaGetSymbolAddress((void**)&kl,  g_kl);
    cudaGetSymbolAddress((void**)&vh,  g_vh);  cudaGetSymbolAddress((void**)&vl,  g_vl);
    cudaGetSymbolAddress((void**)&S,   g_S);
    cudaGetSymbolAddress((void**)&Ph,  g_Ph);  cudaGetSymbolAddress((void**)&Pl,  g_Pl);
    cudaGetSymbolAddress((void**)&aoh, g_aoh); cudaGetSymbolAddress((void**)&aol, g_aol);
    cudaGetSymbolAddress((void**)&f1,  g_f1);  cudaGetSymbolAddress((void**)&f2,  g_f2);
    cudaGetSymbolAddress((void**)&f1h, g_f1h); cudaGetSymbolAddress((void**)&f1l, g_f1l);
    cudaGetSymbolAddress((void**)&Wqh, w_qh);  cudaGetSymbolAddress((void**)&Wql, w_ql);
    cudaGetSymbolAddress((void**)&Wkh, w_kh);  cudaGetSymbolAddress((void**)&Wkl, w_kl);
    cudaGetSymbolAddress((void**)&Wvh, w_vh);  cudaGetSymbolAddress((void**)&Wvl, w_vl);
    cudaGetSymbolAddress((void**)&Woh, w_oh);  cudaGetSymbolAddress((void**)&Wol, w_ol);
    cudaGetSymbolAddress((void**)&Wih, w_ih);  cudaGetSymbolAddress((void**)&Wil, w_il);
    cudaGetSymbolAddress((void**)&Wgh, w_gh);  cudaGetSymbolAddress((void**)&Wgl, w_gl);
    cudaGetSymbolAddress((void**)&Wfoh, w_foh); cudaGetSymbolAddress((void**)&Wfol, w_fol);
    cudaGetSymbolAddress((void**)&Weh, w_eh);  cudaGetSymbolAddress((void**)&Wel, w_el);

    auto cvt = [](const float* in, bf16* h, bf16* l, size_t n) {
        cvt_pair_kernel<<<(unsigned)(n / 1024), 256>>>(in, h, l);
    };

    // ---- weight pre-split (captured; runs each replay) ----
    cvt(wq,  Wqh,  Wql,  (size_t)NLAYER * DMODEL * INNERD);
    cvt(wk,  Wkh,  Wkl,  (size_t)NLAYER * DMODEL * DHEAD);
    cvt(wv,  Wvh,  Wvl,  (size_t)NLAYER * DMODEL * DHEAD);
    cvt(wo,  Woh,  Wol,  (size_t)NLAYER * INNERD * DMODEL);
    cvt(wi,  Wih,  Wil,  (size_t)NLAYER * DMODEL * FFI);
    cvt(wg,  Wgh,  Wgl,  (size_t)NLAYER * DMODEL * FFI);
    cvt(wfo, Wfoh, Wfol, (size_t)NLAYER * FFI * DMODEL);
    cvt(emb, Weh,  Wel,  (size_t)VOCAB * DMODEL);

    embed_kernel<<<NT, 256>>>(tokens, emb, x);

    for (int l = 0; l < NLAYER; ++l) {
        const size_t oq  = (size_t)l * DMODEL * INNERD;
        const size_t okv = (size_t)l * DMODEL * DHEAD;
        const size_t oi  = (size_t)l * DMODEL * FFI;
        const size_t ofo = (size_t)l * FFI * DMODEL;

        // --- attention ---
        rmsnorm_pair_kernel<<<NT, 256>>>(x, attn_gamma + (size_t)l * DMODEL, hh, hl);
        launch_gemm<0, 3>(hh, hl, Wqh + oq, Wql + oq, nullptr, qh, ql,
                          NT, INNERD, DMODEL, DMODEL, INNERD, INNERD, 1, 1, 0, 0, 0);
        cudaMemsetAsync(k, 0, NT * DHEAD * sizeof(float));
        cudaMemsetAsync(v, 0, NT * DHEAD * sizeof(float));
        launch_gemm<0, 2>(hh, hl, Wkh + okv, Wkl + okv, k, nullptr, nullptr,
                          NT, DHEAD, DMODEL, DMODEL, DHEAD, DHEAD, 8, 8, 0, 0, 0);
        launch_gemm<0, 2>(hh, hl, Wvh + okv, Wvl + okv, v, nullptr, nullptr,
                          NT, DHEAD, DMODEL, DMODEL, DHEAD, DHEAD, 8, 8, 0, 0, 0);
        cvt(k, kh, kl, (size_t)NT * DHEAD);
        cvt(v, vh, vl, (size_t)NT * DHEAD);
        // S[h] = Q_h @ K^T   (head batch over z; MQA: shared K)
        launch_gemm<1, 0>(qh, ql, kh, kl, S, nullptr, nullptr,
                          NT, NT, DHEAD, INNERD, DHEAD, NT,
                          NHEAD, 1, (size_t)DHEAD, 0, (size_t)NT * NT);
        softmax_kernel<<<dim3(NT, NHEAD), 256>>>(S, Ph, Pl);
        // O_h = P_h @ V  -> bf16 pair straight into ao
        launch_gemm<0, 3>(Ph, Pl, vh, vl, nullptr, aoh, aol,
                          NT, DHEAD, NT, NT, DHEAD, INNERD,
                          NHEAD, 1, (size_t)NT * NT, 0, (size_t)DHEAD);
        launch_gemm<0, 1>(aoh, aol, Woh + oq, Wol + oq, x, nullptr, nullptr,
                          NT, DMODEL, INNERD, INNERD, DMODEL, DMODEL, 1, 1, 0, 0, 0);

        // --- SwiGLU FFN ---
        rmsnorm_pair_kernel<<<NT, 256>>>(x, ff_gamma + (size_t)l * DMODEL, hh, hl);
        launch_gemm<0, 0>(hh, hl, Wih + oi, Wil + oi, f1, nullptr, nullptr,
                          NT, FFI, DMODEL, DMODEL, FFI, FFI, 1, 1, 0, 0, 0);
        launch_gemm<0, 0>(hh, hl, Wgh + oi, Wgl + oi, f2, nullptr, nullptr,
                          NT, FFI, DMODEL, DMODEL, FFI, FFI, 1, 1, 0, 0, 0);
        silu_pair_kernel<<<(NT * FFI) / 256, 256>>>(f1, f2, f1h, f1l);
        launch_gemm<0, 1>(f1h, f1l, Wfoh + ofo, Wfol + ofo, x, nullptr, nullptr,
                          NT, DMODEL, FFI, FFI, DMODEL, DMODEL, 1, 1, 0, 0, 0);
    }

    // --- final norm + tied-embedding logits ---
    rmsnorm_pair_kernel<<<NT, 256>>>(x, final_gamma, hh, hl);
    launch_gemm<1, 0>(hh, hl, Weh, Wel, out, nullptr, nullptr,
                      NT, VOCAB, DMODEL, DMODEL, DMODEL, VOCAB, 1, 1, 0, 0, 0);
}

// round 8
// speedup vs baseline: 4.6928x; 1.0190x over previous
#include <cuda_runtime.h>
#include <cuda_bf16.h>
#include <cstdint>
#include <math.h>

#define NT      2048
#define DMODEL  2048
#define NHEAD   16
#define DHEAD   128
#define INNERD  2048
#define FFI     8192
#define VOCAB   32000
#define NLAYER  4
#define EPSF    1e-5f
#define MASKV   1e-10f
#define KT      32
#define ASTR    40     // [row][k] smem stride (elems) for A and trans-B tiles
#define BSTRN   136    // [k][n] smem stride (elems) for NN B tiles
#define L2E     1.4426950408889634f

typedef __nv_bfloat16 bf16;

// ---------------- scratch (static device globals; no allocations) ----------------
__device__ float g_x [NT * DMODEL];
__device__ bf16  g_hh[NT * DMODEL], g_hl[NT * DMODEL];
__device__ bf16  g_qh[NT * INNERD], g_ql[NT * INNERD];
__device__ float g_kv [NT * 256];                          // fused [k | v] fp32
__device__ bf16  g_kvh[NT * 256], g_kvl[NT * 256];         // fused [k | v] pairs
__device__ float g_suf[NT * DHEAD];                        // suffixV
__device__ float g_c  [NHEAD * NT];                        // per-row masked prob
__device__ float g_S [(size_t)NHEAD * NT * NT];
__device__ bf16  g_Ph[(size_t)NHEAD * NT * NT], g_Pl[(size_t)NHEAD * NT * NT];
__device__ bf16  g_aoh[NT * INNERD], g_aol[NT * INNERD];
__device__ float g_f1[NT * FFI], g_f2[NT * FFI];           // g_f1 reused as PV fp32 out
__device__ bf16  g_f1h[NT * FFI], g_f1l[NT * FFI];
// pre-split weights (layouts as given by reference)
__device__ bf16 w_qh [NLAYER * DMODEL * INNERD], w_ql [NLAYER * DMODEL * INNERD];
__device__ bf16 w_kvh[NLAYER * DMODEL * 256],    w_kvl[NLAYER * DMODEL * 256];   // interleaved wk|wv
__device__ bf16 w_oh [NLAYER * INNERD * DMODEL], w_ol [NLAYER * INNERD * DMODEL];
__device__ bf16 w_ih [(size_t)NLAYER * DMODEL * FFI], w_il [(size_t)NLAYER * DMODEL * FFI];
__device__ bf16 w_gh [(size_t)NLAYER * DMODEL * FFI], w_gl [(size_t)NLAYER * DMODEL * FFI];
__device__ bf16 w_foh[(size_t)NLAYER * FFI * DMODEL], w_fol[(size_t)NLAYER * FFI * DMODEL];
__device__ bf16 w_eh [(size_t)VOCAB * DMODEL], w_el [(size_t)VOCAB * DMODEL];

// ---------------- helpers ----------------
__device__ __forceinline__ void cpa16(uint32_t dst, const void* src) {
    asm volatile("cp.async.cg.shared.global [%0],[%1],16;" :: "r"(dst), "l"(src));
}
__device__ __forceinline__ void ldsm4(uint32_t* r, uint32_t a) {
    asm volatile("ldmatrix.sync.aligned.m8n8.x4.shared.b16 {%0,%1,%2,%3},[%4];"
                 : "=r"(r[0]), "=r"(r[1]), "=r"(r[2]), "=r"(r[3]) : "r"(a));
}
__device__ __forceinline__ void ldsm4t(uint32_t* r, uint32_t a) {
    asm volatile("ldmatrix.sync.aligned.m8n8.x4.trans.shared.b16 {%0,%1,%2,%3},[%4];"
                 : "=r"(r[0]), "=r"(r[1]), "=r"(r[2]), "=r"(r[3]) : "r"(a));
}
__device__ __forceinline__ void mma16816(float* c, const uint32_t* a, uint32_t b0, uint32_t b1) {
    asm volatile("mma.sync.aligned.m16n8k16.row.col.f32.bf16.bf16.f32 "
                 "{%0,%1,%2,%3},{%4,%5,%6,%7},{%8,%9},{%0,%1,%2,%3};"
                 : "+f"(c[0]), "+f"(c[1]), "+f"(c[2]), "+f"(c[3])
                 : "r"(a[0]), "r"(a[1]), "r"(a[2]), "r"(a[3]), "r"(b0), "r"(b1));
}
__device__ __forceinline__ void split1(float a, bf16& h, bf16& l) {
    h = __float2bfloat16_rn(a);
    l = __float2bfloat16_rn(a - __bfloat162float(h));
}
__device__ __forceinline__ void split2_store(bf16* hp, bf16* lp, float a, float b) {
    float ha = __bfloat162float(__float2bfloat16_rn(a));
    float hb = __bfloat162float(__float2bfloat16_rn(b));
    __nv_bfloat162 H = __floats2bfloat162_rn(a, b);
    __nv_bfloat162 L = __floats2bfloat162_rn(a - ha, b - hb);
    *(uint32_t*)hp = *(uint32_t*)&H;
    *(uint32_t*)lp = *(uint32_t*)&L;
}

// ---------------- fp32 -> bf16 pair (straight, vectorized) ----------------
__global__ void __launch_bounds__(256) cvt_pair_kernel(const float* __restrict__ in,
                                                       bf16* __restrict__ ho, bf16* __restrict__ lo) {
    size_t i = (size_t)blockIdx.x * 256 + threadIdx.x;
    float4 v = ((const float4*)in)[i];
    bf16 h0, l0, h1, l1, h2, l2, h3, l3;
    split1(v.x, h0, l0); split1(v.y, h1, l1); split1(v.z, h2, l2); split1(v.w, h3, l3);
    __nv_bfloat162 ha = {h0, h1}, hb = {h2, h3}, la = {l0, l1}, lb = {l2, l3};
    uint2 H = {*(uint32_t*)&ha, *(uint32_t*)&hb};
    uint2 L = {*(uint32_t*)&la, *(uint32_t*)&lb};
    ((uint2*)ho)[i] = H;
    ((uint2*)lo)[i] = L;
}

// ---- strided pair cvt: in [R,128] -> out [R,256] at column offset ----
__global__ void __launch_bounds__(256) cvt_pair_cols_kernel(const float* __restrict__ in,
                                                            bf16* __restrict__ ho, bf16* __restrict__ lo,
                                                            int colOff) {
    size_t i = (size_t)blockIdx.x * 256 + threadIdx.x;   // float4 index over [R,128]
    int row = (int)(i >> 5);
    int col = ((int)i & 31) * 4;
    float4 v = ((const float4*)in)[i];
    size_t o = (size_t)row * 256 + colOff + col;
    bf16 h0, l0, h1, l1, h2, l2, h3, l3;
    split1(v.x, h0, l0); split1(v.y, h1, l1); split1(v.z, h2, l2); split1(v.w, h3, l3);
    __nv_bfloat162 ha = {h0, h1}, hb = {h2, h3}, la = {l0, l1}, lb = {l2, l3};
    *(uint32_t*)(ho + o)     = *(uint32_t*)&ha;
    *(uint32_t*)(ho + o + 2) = *(uint32_t*)&hb;
    *(uint32_t*)(lo + o)     = *(uint32_t*)&la;
    *(uint32_t*)(lo + o + 2) = *(uint32_t*)&lb;
}

// ---------------- embedding ----------------
__global__ void embed_kernel(const int* __restrict__ tok, const float* __restrict__ emb,
                             float* __restrict__ x) {
    int n = blockIdx.x;
    const float* src = emb + (size_t)tok[n] * DMODEL;
    float* dst = x + (size_t)n * DMODEL;
    for (int d = threadIdx.x; d < DMODEL; d += blockDim.x) dst[d] = src[d];
}

// ---------------- RMSNorm -> bf16 pair ----------------
__global__ void __launch_bounds__(256) rmsnorm_pair_kernel(const float* __restrict__ x,
                                                           const float* __restrict__ gamma,
                                                           bf16* __restrict__ oh, bf16* __restrict__ ol) {
    int n = blockIdx.x;
    const float* row = x + (size_t)n * DMODEL;
    float s = 0.f;
    for (int d = threadIdx.x; d < DMODEL; d += 256) { float v = row[d]; s += v * v; }
    __shared__ float red[256];
    red[threadIdx.x] = s; __syncthreads();
    #pragma unroll
    for (int k = 128; k > 0; k >>= 1) {
        if (threadIdx.x < k) red[threadIdx.x] += red[threadIdx.x + k];
        __syncthreads();
    }
    float inv = rsqrtf(red[0] * (1.0f / DMODEL) + EPSF);
    for (int d = threadIdx.x; d < DMODEL; d += 256) {
        bf16 h, l; split1(row[d] * inv * gamma[d], h, l);
        oh[(size_t)n * DMODEL + d] = h;
        ol[(size_t)n * DMODEL + d] = l;
    }
}

// ---------------- SwiGLU -> bf16 pair ----------------
__global__ void __launch_bounds__(256) silu_pair_kernel(const float* __restrict__ a,
                                                        const float* __restrict__ b,
                                                        bf16* __restrict__ oh, bf16* __restrict__ ol) {
    size_t i = (size_t)blockIdx.x * 256 + threadIdx.x;
    float bb = b[i];
    bf16 h, l; split1(a[i] * bb / (1.f + __expf(-bb)), h, l);
    oh[i] = h; ol[i] = l;
}

// ---------------- suffixV: suf[i][d] = sum_{j>i} v[j][d]; v strided in g_kv ----------------
__global__ void __launch_bounds__(128) suffixv_kernel(const float* __restrict__ kv,
                                                      float* __restrict__ suf) {
    const int d = threadIdx.x;
    const int lo = blockIdx.x * 128, hi = lo + 128;
    float acc = 0.f;
    for (int j = NT - 1; j >= hi; --j)
        acc += kv[(size_t)j * 256 + 128 + d];
    for (int i = hi - 1; i >= lo; --i) {
        suf[(size_t)i * DHEAD + d] = acc;
        acc += kv[(size_t)i * 256 + 128 + d];
    }
}

// ------- softmax: visible region exact, masked region rank-1 (c stored) -------
__global__ void __launch_bounds__(256) softmax_kernel(const float* __restrict__ S,
                                                      bf16* __restrict__ Ph, bf16* __restrict__ Pl,
                                                      float* __restrict__ C) {
    const int i = blockIdx.x, h = blockIdx.y, tid = threadIdx.x;
    const float* row = S + ((size_t)h * NT + i) * NT;
    __shared__ float sc[NT];
    __shared__ float red[256];
    const float slope = exp2f(-0.5f * (float)(h + 1));
    const float scale = 0.08838834764831845f;
    const int tileEnd = ((i >> 7) + 1) << 7;    // columns the PV GEMM will read

    float mx = MASKV;                            // masked entries participate in max
    for (int j = tid; j <= i; j += 256) {
        float v = row[j] * scale + slope * (float)j;
        sc[j] = v;
        mx = fmaxf(mx, v);
    }
    red[tid] = mx; __syncthreads();
    #pragma unroll
    for (int s = 128; s > 0; s >>= 1) {
        if (tid < s) red[tid] = fmaxf(red[tid], red[tid + s]);
        __syncthreads();
    }
    mx = red[0]; __syncthreads();

    float sum = 0.f;
    for (int j = tid; j <= i; j += 256) {
        float p = exp2f((sc[j] - mx) * L2E);
        sc[j] = p; sum += p;
    }
    red[tid] = sum; __syncthreads();
    #pragma unroll
    for (int s = 128; s > 0; s >>= 1) {
        if (tid < s) red[tid] += red[tid + s];
        __syncthreads();
    }
    const float maskexp = exp2f((MASKV - mx) * L2E);
    const float inv = 1.f / (red[0] + (float)(NT - 1 - i) * maskexp);
    const float c = maskexp * inv;
    if (tid == 0) C[(size_t)h * NT + i] = c;

    bf16* ph = Ph + ((size_t)h * NT + i) * NT;
    bf16* pl = Pl + ((size_t)h * NT + i) * NT;
    for (int j = tid; j < tileEnd; j += 256) {
        if (j <= i) {
            bf16 hh, ll; split1(sc[j] * inv, hh, ll);
            ph[j] = hh; pl[j] = ll;
        } else {
            ph[j] = __float2bfloat16_rn(0.f);
            pl[j] = __float2bfloat16_rn(0.f);
        }
    }
}

// ------- attention output correction + split: ao = pv + c*suffixV -> bf16 pair -------
__global__ void __launch_bounds__(256) ao_fix_kernel(const float* __restrict__ pv,
                                                     const float* __restrict__ C,
                                                     const float* __restrict__ suf,
                                                     bf16* __restrict__ oh, bf16* __restrict__ ol) {
    size_t idx = (size_t)blockIdx.x * 256 + threadIdx.x;   // over NT*INNERD
    int i = (int)(idx >> 11);
    int rem = (int)(idx & 2047);
    int h = rem >> 7, d = rem & 127;
    float v = pv[idx] + C[(size_t)h * NT + i] * suf[(size_t)i * DHEAD + d];
    bf16 hh, ll; split1(v, hh, ll);
    oh[idx] = hh; ol[idx] = ll;
}

// ================= pipelined bf16-split tensor-core GEMM =================
// EPI: 0 store fp32, 1 fp32 +=, 2 atomicAdd (split-K), 3 bf16 pair store.
// CAUSAL: 0 none; 1 skip tiles with colBase>rowBase; 2 cap K at rowBase+128.
template <int TRANSB, int EPI, int CAUSAL>
__global__ void __launch_bounds__(256, 2)
gemm_bf3(const bf16* __restrict__ Ah, const bf16* __restrict__ Al,
         const bf16* __restrict__ Bh, const bf16* __restrict__ Bl,
         float* __restrict__ C, bf16* __restrict__ Ch, bf16* __restrict__ Cl,
         int M, int N, int K, int lda, int ldb, int ldc,
         int kSplit, size_t aZ, size_t bZ, size_t cZ) {
    extern __shared__ __align__(16) char smem[];
    const int tid = threadIdx.x, lane = tid & 31, warp = tid >> 5;
    const int wm = warp >> 2, wn = warp & 3;
    const int rowBase = blockIdx.y * 128, colBase = blockIdx.x * 128;
    if (CAUSAL == 1 && colBase > rowBase) return;
    const int z = blockIdx.z;
    int kStart = 0, kEnd = K;
    if (CAUSAL == 2) kEnd = rowBase + 128 < K ? rowBase + 128 : K;
    if (kSplit > 1) {
        int kl = K / kSplit; kStart = z * kl; kEnd = kStart + kl;
    } else {
        Ah += z * aZ; Al += z * aZ; Bh += z * bZ; Bl += z * bZ;
        if (EPI == 3) { Ch += z * cZ; Cl += z * cZ; } else { C += z * cZ; }
    }
    const int nk = (kEnd - kStart) / KT;
    const uint32_t sb = (uint32_t)__cvta_generic_to_shared(smem);
    const int BUFB = TRANSB ? 10240 : 8704;

    auto load_stage = [&](int s, int kt) {
        uint32_t aOff = sb + s * 20480;
        uint32_t bOff = sb + 40960 + s * 2 * BUFB;
        #pragma unroll
        for (int r = 0; r < 2; ++r) {
            int idx = tid + r * 256;
            int row = idx >> 2, kc = (idx & 3) * 8;
            uint32_t d = aOff + (row * ASTR + kc) * 2;
            const size_t ga = (size_t)(rowBase + row) * lda + kt + kc;
            cpa16(d,         Ah + ga);
            cpa16(d + 10240, Al + ga);
            if (!TRANSB) {
                int kr = idx >> 4, nc = (idx & 15) * 8;
                uint32_t db = bOff + (kr * BSTRN + nc) * 2;
                const size_t gb = (size_t)(kt + kr) * ldb + colBase + nc;
                cpa16(db,        Bh + gb);
                cpa16(db + BUFB, Bl + gb);
            } else {
                int nr = idx >> 2, kc2 = (idx & 3) * 8;
                uint32_t db = bOff + (nr * ASTR + kc2) * 2;
                const size_t gb = (size_t)(colBase + nr) * ldb + kt + kc2;
                cpa16(db,        Bh + gb);
                cpa16(db + BUFB, Bl + gb);
            }
        }
        asm volatile("cp.async.commit_group;");
    };

    float acc[4][4][4];
    #pragma unroll
    for (int i = 0; i < 4; ++i)
        #pragma unroll
        for (int j = 0; j < 4; ++j)
            #pragma unroll
            for (int v = 0; v < 4; ++v) acc[i][j][v] = 0.f;

    const int l15 = lane & 15, lhi = (lane >> 4) * 8;

    load_stage(0, kStart);

    for (int it = 0; it < nk; ++it) {
        const int s = it & 1;
        if (it + 1 < nk) {
            load_stage((it + 1) & 1, kStart + (it + 1) * KT);
            asm volatile("cp.async.wait_group 1;");
        } else {
            asm volatile("cp.async.wait_group 0;");
        }
        __syncthreads();

        const uint32_t aBase = sb + s * 20480 + ((wm * 64 + l15) * ASTR + lhi) * 2;
        const uint32_t bOff  = sb + 40960 + s * 2 * BUFB;

        #pragma unroll
        for (int ks = 0; ks < KT; ks += 16) {
            uint32_t aH[4][4], aL[4][4], bH[2][4], bL[2][4];
            #pragma unroll
            for (int mt = 0; mt < 4; ++mt)
                ldsm4(aH[mt], aBase + ks * 2 + mt * (16 * ASTR * 2));
            if (!TRANSB) {
                uint32_t bBase = bOff + ((l15 + ks) * BSTRN + wn * 32 + lhi) * 2;
                #pragma unroll
                for (int p = 0; p < 2; ++p) ldsm4t(bH[p], bBase + p * 32);
            } else {
                #pragma unroll
                for (int p = 0; p < 2; ++p)
                    ldsm4(bH[p], bOff + ((wn * 32 + p * 16 + l15) * ASTR + ks + lhi) * 2);
            }
            #pragma unroll
            for (int mt = 0; mt < 4; ++mt)
                #pragma unroll
                for (int nt = 0; nt < 4; ++nt) {
                    int p = nt >> 1, su = nt & 1;
                    uint32_t b0 = TRANSB ? bH[p][su]     : bH[p][2 * su];
                    uint32_t b1 = TRANSB ? bH[p][su + 2] : bH[p][2 * su + 1];
                    mma16816(acc[mt][nt], aH[mt], b0, b1);
                }
            if (!TRANSB) {
                uint32_t bBase = bOff + BUFB + ((l15 + ks) * BSTRN + wn * 32 + lhi) * 2;
                #pragma unroll
                for (int p = 0; p < 2; ++p) ldsm4t(bL[p], bBase + p * 32);
            } else {
                #pragma unroll
                for (int p = 0; p < 2; ++p)
                    ldsm4(bL[p], bOff + BUFB + ((wn * 32 + p * 16 + l15) * ASTR + ks + lhi) * 2);
            }
            #pragma unroll
            for (int mt = 0; mt < 4; ++mt)
                #pragma unroll
                for (int nt = 0; nt < 4; ++nt) {
                    int p = nt >> 1, su = nt & 1;
                    uint32_t b0 = TRANSB ? bL[p][su]     : bL[p][2 * su];
                    uint32_t b1 = TRANSB ? bL[p][su + 2] : bL[p][2 * su + 1];
                    mma16816(acc[mt][nt], aH[mt], b0, b1);
                }
            #pragma unroll
            for (int mt = 0; mt < 4; ++mt)
                ldsm4(aL[mt], aBase + 10240 + ks * 2 + mt * (16 * ASTR * 2));
            #pragma unroll
            for (int mt = 0; mt < 4; ++mt)
                #pragma unroll
                for (int nt = 0; nt < 4; ++nt) {
                    int p = nt >> 1, su = nt & 1;
                    uint32_t b0 = TRANSB ? bH[p][su]     : bH[p][2 * su];
                    uint32_t b1 = TRANSB ? bH[p][su + 2] : bH[p][2 * su + 1];
                    mma16816(acc[mt][nt], aL[mt], b0, b1);
                }
        }
        __syncthreads();
    }

    // ---------- epilogue ----------
    const int r0 = rowBase + wm * 64 + (lane >> 2);
    const int c0 = colBase + wn * 32 + (lane & 3) * 2;
    #pragma unroll
    for (int mt = 0; mt < 4; ++mt) {
        #pragma unroll
        for (int nt = 0; nt < 4; ++nt) {
            int r = r0 + mt * 16, c = c0 + nt * 8;
            if (EPI == 3) {
                split2_store(Ch + (size_t)r * ldc + c,       Cl + (size_t)r * ldc + c,
                             acc[mt][nt][0], acc[mt][nt][1]);
                split2_store(Ch + (size_t)(r + 8) * ldc + c, Cl + (size_t)(r + 8) * ldc + c,
                             acc[mt][nt][2], acc[mt][nt][3]);
            } else if (EPI == 2) {
                atomicAdd(C + (size_t)r * ldc + c,           acc[mt][nt][0]);
                atomicAdd(C + (size_t)r * ldc + c + 1,       acc[mt][nt][1]);
                atomicAdd(C + (size_t)(r + 8) * ldc + c,     acc[mt][nt][2]);
                atomicAdd(C + (size_t)(r + 8) * ldc + c + 1, acc[mt][nt][3]);
            } else {
                float2* p0 = (float2*)(C + (size_t)r * ldc + c);
                float2* p1 = (float2*)(C + (size_t)(r + 8) * ldc + c);
                if (EPI == 1) {
                    float2 t0 = *p0, t1 = *p1;
                    t0.x += acc[mt][nt][0]; t0.y += acc[mt][nt][1];
                    t1.x += acc[mt][nt][2]; t1.y += acc[mt][nt][3];
                    *p0 = t0; *p1 = t1;
                } else {
                    *p0 = make_float2(acc[mt][nt][0], acc[mt][nt][1]);
                    *p1 = make_float2(acc[mt][nt][2], acc[mt][nt][3]);
                }
            }
        }
    }
}

// ---------------- host-side dispatch ----------------
template <int TRANSB, int EPI, int CAUSAL>
static void launch_gemm(const bf16* Ah, const bf16* Al, const bf16* Bh, const bf16* Bl,
                        float* C, bf16* Ch, bf16* Cl,
                        int M, int N, int K, int lda, int ldb, int ldc,
                        int Z, int kSplit, size_t aZ, size_t bZ, size_t cZ) {
    const int smem = 40960 + 4 * (TRANSB ? 10240 : 8704);
    cudaFuncSetAttribute(gemm_bf3<TRANSB, EPI, CAUSAL>, cudaFuncAttributeMaxDynamicSharedMemorySize, smem);
    dim3 grid(N / 128, M / 128, Z);
    gemm_bf3<TRANSB, EPI, CAUSAL><<<grid, 256, smem>>>(Ah, Al, Bh, Bl, C, Ch, Cl,
                                                       M, N, K, lda, ldb, ldc, kSplit, aZ, bZ, cZ);
}

extern "C" void kernel_launch(void* const* d_in, const int* in_sizes, int n_in,
                              void* d_out, int out_size) {
    const int*   tokens      = (const int*)  d_in[0];
    const float* emb         = (const float*)d_in[1];
    const float* attn_gamma  = (const float*)d_in[2];
    const float* wq          = (const float*)d_in[3];
    const float* wk          = (const float*)d_in[4];
    const float* wv          = (const float*)d_in[5];
    const float* wo          = (const float*)d_in[6];
    const float* ff_gamma    = (const float*)d_in[7];
    const float* wi          = (const float*)d_in[8];
    const float* wg          = (const float*)d_in[9];
    const float* wfo         = (const float*)d_in[10];
    const float* final_gamma = (const float*)d_in[11];
    float* out = (float*)d_out;

    float *x, *kv, *suf, *c, *S, *f1, *f2;
    bf16 *hh, *hl, *qh, *ql, *kvh, *kvl, *Ph, *Pl, *aoh, *aol, *f1h, *f1l;
    bf16 *Wqh, *Wql, *Wkvh, *Wkvl, *Woh, *Wol, *Wih, *Wil, *Wgh, *Wgl, *Wfoh, *Wfol, *Weh, *Wel;
    cudaGetSymbolAddress((void**)&x,    g_x);
    cudaGetSymbolAddress((void**)&hh,   g_hh);  cudaGetSymbolAddress((void**)&hl,  g_hl);
    cudaGetSymbolAddress((void**)&qh,   g_qh);  cudaGetSymbolAddress((void**)&ql,  g_ql);
    cudaGetSymbolAddress((void**)&kv,   g_kv);
    cudaGetSymbolAddress((void**)&kvh,  g_kvh); cudaGetSymbolAddress((void**)&kvl, g_kvl);
    cudaGetSymbolAddress((void**)&suf,  g_suf); cudaGetSymbolAddress((void**)&c,   g_c);
    cudaGetSymbolAddress((void**)&S,    g_S);
    cudaGetSymbolAddress((void**)&Ph,   g_Ph);  cudaGetSymbolAddress((void**)&Pl,  g_Pl);
    cudaGetSymbolAddress((void**)&aoh,  g_aoh); cudaGetSymbolAddress((void**)&aol, g_aol);
    cudaGetSymbolAddress((void**)&f1,   g_f1);  cudaGetSymbolAddress((void**)&f2,  g_f2);
    cudaGetSymbolAddress((void**)&f1h,  g_f1h); cudaGetSymbolAddress((void**)&f1l, g_f1l);
    cudaGetSymbolAddress((void**)&Wqh,  w_qh);  cudaGetSymbolAddress((void**)&Wql, w_ql);
    cudaGetSymbolAddress((void**)&Wkvh, w_kvh); cudaGetSymbolAddress((void**)&Wkvl, w_kvl);
    cudaGetSymbolAddress((void**)&Woh,  w_oh);  cudaGetSymbolAddress((void**)&Wol, w_ol);
    cudaGetSymbolAddress((void**)&Wih,  w_ih);  cudaGetSymbolAddress((void**)&Wil, w_il);
    cudaGetSymbolAddress((void**)&Wgh,  w_gh);  cudaGetSymbolAddress((void**)&Wgl, w_gl);
    cudaGetSymbolAddress((void**)&Wfoh, w_foh); cudaGetSymbolAddress((void**)&Wfol, w_fol);
    cudaGetSymbolAddress((void**)&Weh,  w_eh);  cudaGetSymbolAddress((void**)&Wel, w_el);

    auto cvt = [](const float* in, bf16* h, bf16* l, size_t n) {
        cvt_pair_kernel<<<(unsigned)(n / 1024), 256>>>(in, h, l);
    };

    // ---- weight pre-split (captured; runs each replay) ----
    cvt(wq,  Wqh,  Wql,  (size_t)NLAYER * DMODEL * INNERD);
    cvt(wo,  Woh,  Wol,  (size_t)NLAYER * INNERD * DMODEL);
    cvt(wi,  Wih,  Wil,  (size_t)NLAYER * DMODEL * FFI);
    cvt(wg,  Wgh,  Wgl,  (size_t)NLAYER * DMODEL * FFI);
    cvt(wfo, Wfoh, Wfol, (size_t)NLAYER * FFI * DMODEL);
    cvt(emb, Weh,  Wel,  (size_t)VOCAB * DMODEL);
    for (int l = 0; l < NLAYER; ++l) {
        const size_t okv = (size_t)l * DMODEL * DHEAD;
        const size_t okvW = (size_t)l * DMODEL * 256;
        cvt_pair_cols_kernel<<<(DMODEL * DHEAD) / 1024, 256>>>(wk + okv, Wkvh + okvW, Wkvl + okvW, 0);
        cvt_pair_cols_kernel<<<(DMODEL * DHEAD) / 1024, 256>>>(wv + okv, Wkvh + okvW, Wkvl + okvW, 128);
    }

    embed_kernel<<<NT, 256>>>(tokens, emb, x);

    for (int l = 0; l < NLAYER; ++l) {
        const size_t oq   = (size_t)l * DMODEL * INNERD;
        const size_t okvW = (size_t)l * DMODEL * 256;
        const size_t oi   = (size_t)l * DMODEL * FFI;
        const size_t ofo  = (size_t)l * FFI * DMODEL;

        // --- attention ---
        rmsnorm_pair_kernel<<<NT, 256>>>(x, attn_gamma + (size_t)l * DMODEL, hh, hl);
        launch_gemm<0, 3, 0>(hh, hl, Wqh + oq, Wql + oq, nullptr, qh, ql,
                             NT, INNERD, DMODEL, DMODEL, INNERD, INNERD, 1, 1, 0, 0, 0);
        cudaMemsetAsync(kv, 0, NT * 256 * sizeof(float));
        launch_gemm<0, 2, 0>(hh, hl, Wkvh + okvW, Wkvl + okvW, kv, nullptr, nullptr,
                             NT, 256, DMODEL, DMODEL, 256, 256, 8, 8, 0, 0, 0);
        cvt(kv, kvh, kvl, (size_t)NT * 256);
        suffixv_kernel<<<NT / 128, 128>>>(kv, suf);
        // S[h] = Q_h @ K^T  (skip strictly-upper tiles)
        launch_gemm<1, 0, 1>(qh, ql, kvh, kvl, S, nullptr, nullptr,
                             NT, NT, DHEAD, INNERD, 256, NT,
                             NHEAD, 1, (size_t)DHEAD, 0, (size_t)NT * NT);
        softmax_kernel<<<dim3(NT, NHEAD), 256>>>(S, Ph, Pl, c);
        // pv = P_h @ V  (K capped at diagonal; fp32 into f1 scratch)
        launch_gemm<0, 0, 2>(Ph, Pl, kvh + 128, kvl + 128, f1, nullptr, nullptr,
                             NT, DHEAD, NT, NT, 256, INNERD,
                             NHEAD, 1, (size_t)NT * NT, 0, (size_t)DHEAD);
        ao_fix_kernel<<<(NT * INNERD) / 256, 256>>>(f1, c, suf, aoh, aol);
        launch_gemm<0, 1, 0>(aoh, aol, Woh + oq, Wol + oq, x, nullptr, nullptr,
                             NT, DMODEL, INNERD, INNERD, DMODEL, DMODEL, 1, 1, 0, 0, 0);

        // --- SwiGLU FFN ---
        rmsnorm_pair_kernel<<<NT, 256>>>(x, ff_gamma + (size_t)l * DMODEL, hh, hl);
        launch_gemm<0, 0, 0>(hh, hl, Wih + oi, Wil + oi, f1, nullptr, nullptr,
                             NT, FFI, DMODEL, DMODEL, FFI, FFI, 1, 1, 0, 0, 0);
        launch_gemm<0, 0, 0>(hh, hl, Wgh + oi, Wgl + oi, f2, nullptr, nullptr,
                             NT, FFI, DMODEL, DMODEL, FFI, FFI, 1, 1, 0, 0, 0);
        silu_pair_kernel<<<(NT * FFI) / 256, 256>>>(f1, f2, f1h, f1l);
        launch_gemm<0, 1, 0>(f1h, f1l, Wfoh + ofo, Wfol + ofo, x, nullptr, nullptr,
                             NT, DMODEL, FFI, FFI, DMODEL, DMODEL, 1, 1, 0, 0, 0);
    }

    // --- final norm + tied-embedding logits ---
    rmsnorm_pair_kernel<<<NT, 256>>>(x, final_gamma, hh, hl);
    launch_gemm<1, 0, 0>(hh, hl, Weh, Wel, out, nullptr, nullptr,
                         NT, VOCAB, DMODEL, DMODEL, DMODEL, VOCAB, 1, 1, 0, 0, 0);
}